// round 12
// baseline (speedup 1.0000x reference)
#include <cuda_runtime.h>
#include <cuda_bf16.h>
#include <cstdint>
#include <cstddef>

// ---------------------------------------------------------------------------
// RQ-VAE forward, fp32. Reference = fp32 (TF32 refuted: flips scale with
// input perturbation). Encoder K>=512 layers emulate Eigen/XLA-CPU
// kc-blocked accumulation (KC=256): per-chunk ascending-k fused-fma chains
// computed by SEPARATE partial-GEMM launches, folded by fp32 adds, bias
// added after the full sum. Chunking via multi-launch keeps the GEMM binary
// identical to the R4-R9 proven 256-thread kernel (infra de-risk).
// Output layout (f32): out[B*768] | rq_loss[1] | indices[B*4] | x_q[B*32]
// NOTE: everything after rq_loss in d_out is only 4-byte aligned (the +1).
// ---------------------------------------------------------------------------

#define BATCH 65536
#define NSTAGE 4
#define CBSIZE 256
#define EDIM 32

// Scratch: 3 slots of B*512 (enc0 partials; later reused), z, zq, loss.
//   slotP0 (B*512): enc0 c0 -> y0 (in-place combine) -> d3r (dec2 out)
//   slotP1 (B*512): enc0 c1 -> [enc1 q0 -> y1 (B*256) | enc1 q1] -> d2r
//   slotP2 (B*512): enc0 c2 -> y2 (B*128) -> d1r (B*128)
//   slotZ  (B*32):  z
//   slotZQ (B*32):  zq (aligned x_q copy for decoder)
#define SCRATCH_ELTS ((size_t)BATCH * (512 * 3 + 32 + 32) + 16)
__device__ __align__(16) float g_scratch[SCRATCH_ELTS];

// ---------------------------------------------------------------------------
// GEMM: C[m][n] = (relu)( sum_{k<K} A[m][k]*W[n][k] (+ bias[n]) )
// A row-major with leading dim lda, W row-major with leading dim ldw.
// Monolithic ascending-k fused-fma chain per output (proven R4-R9 binary).
// ---------------------------------------------------------------------------
template <int BM, int BN, int BK, int TM, int TN, bool RELU, bool HAS_BIAS>
__global__ void __launch_bounds__((BM / TM) * (BN / TN))
gemm_bias(const float* __restrict__ A, int lda,
          const float* __restrict__ W, int ldw,
          const float* __restrict__ bias, float* __restrict__ C,
          int M, int N, int K)
{
    constexpr int THREADS = (BM / TM) * (BN / TN);
    __shared__ __align__(16) float As[BK][BM + 4];
    __shared__ __align__(16) float Ws[BK][BN + 4];

    const int tid = threadIdx.x;
    const int bm = blockIdx.y * BM;
    const int bn = blockIdx.x * BN;

    const int tx = tid % (BN / TN);
    const int ty = tid / (BN / TN);

    float acc[TM][TN];
#pragma unroll
    for (int i = 0; i < TM; i++)
#pragma unroll
        for (int j = 0; j < TN; j++) acc[i][j] = 0.f;

    for (int k0 = 0; k0 < K; k0 += BK) {
        for (int i = tid * 4; i < BM * BK; i += THREADS * 4) {
            int m = i / BK, k = i % BK;
            float4 v = *reinterpret_cast<const float4*>(
                &A[(size_t)(bm + m) * lda + k0 + k]);
            As[k + 0][m] = v.x; As[k + 1][m] = v.y;
            As[k + 2][m] = v.z; As[k + 3][m] = v.w;
        }
        for (int i = tid * 4; i < BN * BK; i += THREADS * 4) {
            int n = i / BK, k = i % BK;
            float4 v = *reinterpret_cast<const float4*>(
                &W[(size_t)(bn + n) * ldw + k0 + k]);
            Ws[k + 0][n] = v.x; Ws[k + 1][n] = v.y;
            Ws[k + 2][n] = v.z; Ws[k + 3][n] = v.w;
        }
        __syncthreads();

#pragma unroll
        for (int kk = 0; kk < BK; kk++) {
            float ra[TM], rw[TN];
#pragma unroll
            for (int i = 0; i < TM; i += 4)
                *reinterpret_cast<float4*>(&ra[i]) =
                    *reinterpret_cast<const float4*>(&As[kk][ty * TM + i]);
#pragma unroll
            for (int j = 0; j < TN; j += 4)
                *reinterpret_cast<float4*>(&rw[j]) =
                    *reinterpret_cast<const float4*>(&Ws[kk][tx * TN + j]);
#pragma unroll
            for (int i = 0; i < TM; i++)
#pragma unroll
                for (int j = 0; j < TN; j++)
                    acc[i][j] = fmaf(ra[i], rw[j], acc[i][j]);
        }
        __syncthreads();
    }

#pragma unroll
    for (int i = 0; i < TM; i++) {
        const size_t m = (size_t)(bm + ty * TM + i);
#pragma unroll
        for (int j = 0; j < TN; j++) {
            const int n = bn + tx * TN + j;
            float v = acc[i][j];
            if (HAS_BIAS) v = __fadd_rn(v, bias[n]);
            if (RELU) v = fmaxf(v, 0.f);
            C[m * N + n] = v;
        }
    }
}

// ---------------------------------------------------------------------------
// Chunk folds: out = relu( fl(...fl(c0+c1)...) + bias[n] ), elementwise.
// Writes in-place into c0's buffer (same index -> safe).
// ---------------------------------------------------------------------------
__global__ void __launch_bounds__(256)
combine3_relu(float* __restrict__ c0, const float* __restrict__ c1,
              const float* __restrict__ c2, const float* __restrict__ bias,
              int total, int N)
{
    int i = blockIdx.x * blockDim.x + threadIdx.x;
    if (i >= total) return;
    int n = i % N;
    float v = __fadd_rn(__fadd_rn(c0[i], c1[i]), c2[i]);
    v = __fadd_rn(v, bias[n]);
    c0[i] = fmaxf(v, 0.f);
}

__global__ void __launch_bounds__(256)
combine2_relu(float* __restrict__ c0, const float* __restrict__ c1,
              const float* __restrict__ bias, int total, int N)
{
    int i = blockIdx.x * blockDim.x + threadIdx.x;
    if (i >= total) return;
    int n = i % N;
    float v = __fadd_rn(c0[i], c1[i]);
    v = __fadd_rn(v, bias[n]);
    c0[i] = fmaxf(v, 0.f);
}

// ---------------------------------------------------------------------------
// Residual VQ (frozen bit-for-bit since R8):
//   esq/lsq: 4-lane partials + pairwise combine
//   dot:  sequential ascending fused fma
//   dist = fl( fl(lsq+esq) - fl(2*dot) )
//   x_res = fl( r + fl(e - r) );  xq += x_res;  r -= x_res
// ---------------------------------------------------------------------------
__device__ __forceinline__ float sumsq_neon(const float* v)
{
    float l0 = 0.f, l1 = 0.f, l2 = 0.f, l3 = 0.f;
#pragma unroll
    for (int i = 0; i < EDIM / 4; i++) {
        l0 = __fadd_rn(l0, __fmul_rn(v[4 * i + 0], v[4 * i + 0]));
        l1 = __fadd_rn(l1, __fmul_rn(v[4 * i + 1], v[4 * i + 1]));
        l2 = __fadd_rn(l2, __fmul_rn(v[4 * i + 2], v[4 * i + 2]));
        l3 = __fadd_rn(l3, __fmul_rn(v[4 * i + 3], v[4 * i + 3]));
    }
    return __fadd_rn(__fadd_rn(l0, l1), __fadd_rn(l2, l3));
}

__global__ void __launch_bounds__(256)
vq_kernel(const float* __restrict__ z, const float* __restrict__ codebooks,
          float* __restrict__ xq_aligned, float* __restrict__ xq_out,
          float* __restrict__ idx_out, float* __restrict__ loss_accum)
{
    __shared__ __align__(16) float cb[CBSIZE * EDIM];
    __shared__ float cn[CBSIZE];

    const int tid = threadIdx.x;
    const size_t row = (size_t)blockIdx.x * blockDim.x + tid;

    float r[EDIM], xq[EDIM];
#pragma unroll
    for (int d = 0; d < EDIM; d++) {
        r[d] = z[row * EDIM + d];
        xq[d] = 0.f;
    }

    float lsum[NSTAGE];

    for (int s = 0; s < NSTAGE; s++) {
        __syncthreads();
        for (int i = tid; i < CBSIZE * EDIM / 4; i += blockDim.x)
            reinterpret_cast<float4*>(cb)[i] =
                reinterpret_cast<const float4*>(codebooks + (size_t)s * CBSIZE * EDIM)[i];
        __syncthreads();
        if (tid < CBSIZE)
            cn[tid] = sumsq_neon(&cb[tid * EDIM]);
        __syncthreads();

        float lsq = sumsq_neon(r);

        float best = __int_as_float(0x7f800000);  // +inf
        int bi = 0;
        for (int j = 0; j < CBSIZE; j++) {
            float dot = 0.f;
#pragma unroll
            for (int d = 0; d < EDIM; d++)
                dot = fmaf(r[d], cb[j * EDIM + d], dot);
            float t1 = __fadd_rn(lsq, cn[j]);
            float t2 = __fmul_rn(2.0f, dot);
            float dist = __fsub_rn(t1, t2);
            if (dist < best) { best = dist; bi = j; }
        }

        float ls = 0.f;
#pragma unroll
        for (int d = 0; d < EDIM; d++) {
            float e = cb[bi * EDIM + d];
            float t = __fsub_rn(e, r[d]);
            ls = __fadd_rn(ls, __fmul_rn(t, t));
            float xres = __fadd_rn(r[d], t);
            xq[d] = __fadd_rn(xq[d], xres);
            r[d] = __fsub_rn(r[d], xres);
        }
        lsum[s] = ls;
        idx_out[row * NSTAGE + s] = (float)bi;
    }

#pragma unroll
    for (int d = 0; d < EDIM; d += 4) {
        float4 v = make_float4(xq[d], xq[d + 1], xq[d + 2], xq[d + 3]);
        *reinterpret_cast<float4*>(&xq_aligned[row * EDIM + d]) = v;
        xq_out[row * EDIM + d + 0] = xq[d + 0];
        xq_out[row * EDIM + d + 1] = xq[d + 1];
        xq_out[row * EDIM + d + 2] = xq[d + 2];
        xq_out[row * EDIM + d + 3] = xq[d + 3];
    }

#pragma unroll
    for (int s = 0; s < NSTAGE; s++) {
        float v = lsum[s];
#pragma unroll
        for (int o = 16; o > 0; o >>= 1)
            v += __shfl_down_sync(0xffffffffu, v, o);
        if ((tid & 31) == 0) atomicAdd(&loss_accum[s], v);
    }
}

__global__ void zero_loss(float* acc)
{
    if (threadIdx.x < NSTAGE) acc[threadIdx.x] = 0.f;
}

__global__ void finalize_loss(const float* __restrict__ acc, float* __restrict__ out_loss)
{
    if (threadIdx.x == 0) {
        float t = acc[0] + acc[1] + acc[2] + acc[3];
        *out_loss = t * (1.25f / (4.0f * (float)BATCH * (float)EDIM));
    }
}

// ---------------------------------------------------------------------------
// Launch
// ---------------------------------------------------------------------------
extern "C" void kernel_launch(void* const* d_in, const int* in_sizes, int n_in,
                              void* d_out, int out_size)
{
    float* scratch = nullptr;
    cudaGetSymbolAddress((void**)&scratch, g_scratch);
    if (!scratch) return;

    const float* x   = (const float*)d_in[0];
    const float* ew0 = (const float*)d_in[1];
    const float* eb0 = (const float*)d_in[2];
    const float* ew1 = (const float*)d_in[3];
    const float* eb1 = (const float*)d_in[4];
    const float* ew2 = (const float*)d_in[5];
    const float* eb2 = (const float*)d_in[6];
    const float* ew3 = (const float*)d_in[7];
    const float* eb3 = (const float*)d_in[8];
    const float* dw0 = (const float*)d_in[9];
    const float* db0 = (const float*)d_in[10];
    const float* dw1 = (const float*)d_in[11];
    const float* db1 = (const float*)d_in[12];
    const float* dw2 = (const float*)d_in[13];
    const float* db2 = (const float*)d_in[14];
    const float* dw3 = (const float*)d_in[15];
    const float* db3 = (const float*)d_in[16];
    const float* cbs = (const float*)d_in[17];

    float* out = (float*)d_out;

    float* slotP0 = scratch;                          // B*512
    float* slotP1 = slotP0 + (size_t)BATCH * 512;     // B*512
    float* slotP2 = slotP1 + (size_t)BATCH * 512;     // B*512
    float* slotZ  = slotP2 + (size_t)BATCH * 512;     // B*32
    float* slotZQ = slotZ + (size_t)BATCH * 32;       // B*32
    float* lacc   = slotZQ + (size_t)BATCH * 32;      // 4

    // Lifetime mapping
    float* y0  = slotP0;                              // enc0 out (combine in-place)
    float* q0  = slotP1;                              // enc1 chunk0 -> y1
    float* q1  = slotP1 + (size_t)BATCH * 256;        // enc1 chunk1
    float* y1  = q0;
    float* y2  = slotP2;                              // enc2 out (B*128)
    float* z   = slotZ;
    float* zq  = slotZQ;
    float* d1r = slotP2;                              // dec0 out (B*128), y2 dead
    float* d2r = slotP1;                              // dec1 out (B*256)
    float* d3r = slotP0;                              // dec2 out (B*512)

    float* out_main = out;                            // B*768 (16B aligned)
    float* out_loss = out + (size_t)BATCH * 768;      // 1
    float* out_idx  = out_loss + 1;                   // B*4  (4B aligned!)
    float* out_xq   = out_idx + (size_t)BATCH * 4;    // B*32 (4B aligned!)

    const int MB = BATCH / 128;  // 512 row-blocks

    zero_loss<<<1, 32>>>(lacc);

    // ---- enc0: K=768 as 3 KC=256 chunks, fold ((c0+c1)+c2)+b, relu ----
    gemm_bias<128, 128, 16, 8, 8, false, false><<<dim3(4, MB), 256>>>(
        x + 0,   768, ew0 + 0,   768, nullptr, slotP0, BATCH, 512, 256);
    gemm_bias<128, 128, 16, 8, 8, false, false><<<dim3(4, MB), 256>>>(
        x + 256, 768, ew0 + 256, 768, nullptr, slotP1, BATCH, 512, 256);
    gemm_bias<128, 128, 16, 8, 8, false, false><<<dim3(4, MB), 256>>>(
        x + 512, 768, ew0 + 512, 768, nullptr, slotP2, BATCH, 512, 256);
    combine3_relu<<<(BATCH * 512 + 255) / 256, 256>>>(
        slotP0, slotP1, slotP2, eb0, BATCH * 512, 512);

    // ---- enc1: K=512 as 2 KC=256 chunks ----
    gemm_bias<128, 128, 16, 8, 8, false, false><<<dim3(2, MB), 256>>>(
        y0 + 0,   512, ew1 + 0,   512, nullptr, q0, BATCH, 256, 256);
    gemm_bias<128, 128, 16, 8, 8, false, false><<<dim3(2, MB), 256>>>(
        y0 + 256, 512, ew1 + 256, 512, nullptr, q1, BATCH, 256, 256);
    combine2_relu<<<(BATCH * 256 + 255) / 256, 256>>>(
        q0, q1, eb1, BATCH * 256, 256);

    // ---- enc2, enc3: K<=256, single chain ----
    gemm_bias<128, 128, 16, 8, 8, true, true><<<dim3(1, MB), 256>>>(
        y1, 256, ew2, 256, eb2, y2, BATCH, 128, 256);
    gemm_bias<128, 32, 32, 8, 4, false, true><<<dim3(1, MB), 128>>>(
        y2, 128, ew3, 128, eb3, z, BATCH, 32, 128);

    // ---- Residual VQ ----
    vq_kernel<<<BATCH / 256, 256>>>(z, cbs, zq, out_xq, out_idx, lacc);
    finalize_loss<<<1, 32>>>(lacc, out_loss);

    // ---- Decoder (downstream of x_q; order noise is smooth ~1e-7) ----
    gemm_bias<128, 128, 16, 8, 8, true, true><<<dim3(1, MB), 256>>>(
        zq, 32, dw0, 32, db0, d1r, BATCH, 128, 32);
    gemm_bias<128, 128, 16, 8, 8, true, true><<<dim3(2, MB), 256>>>(
        d1r, 128, dw1, 128, db1, d2r, BATCH, 256, 128);
    gemm_bias<128, 128, 16, 8, 8, true, true><<<dim3(4, MB), 256>>>(
        d2r, 256, dw2, 256, db2, d3r, BATCH, 512, 256);
    gemm_bias<128, 128, 16, 8, 8, false, true><<<dim3(6, MB), 256>>>(
        d3r, 512, dw3, 512, db3, out_main, BATCH, 768, 512);
}